// round 6
// baseline (speedup 1.0000x reference)
#include <cuda_runtime.h>
#include <cuda_bf16.h>
#include <cstdint>

#define BB 64
#define TLEN 8192
#define DD 64
#define NSTATE 64
#define NCHUNK 64           // chunks per batch
#define BURN 16             // burn-in steps (direction recovery)
#define ROWS 144            // BURN + 128 payload
#define XSTRIDE 146         // padded row stride of transposed X tile (even, reduces STS conflicts)

#define LOG_2PI 1.8378770664093453f

// ---- packed f32x2 helpers (Blackwell FFMA2 path; PTX-only) ----
#define FFMA2_ACC(d, a, b) asm("fma.rn.f32x2 %0, %1, %2, %0;" : "+l"(d) : "l"(a), "l"(b))
#define FFMA2_3(d, a, b, c) asm("fma.rn.f32x2 %0, %1, %2, %3;" : "=l"(d) : "l"(a), "l"(b), "l"(c))
#define ADD2(d, a, b)       asm("add.rn.f32x2 %0, %1, %2;" : "=l"(d) : "l"(a), "l"(b))
#define BCAST2(d, x)        asm("mov.b64 %0, {%1, %1};" : "=l"(d) : "f"(x))
#define UNPACK2(lo, hi, p)  asm("mov.b64 {%0, %1}, %2;" : "=f"(lo), "=f"(hi) : "l"(p))

// ---------------- scratch (static device globals; no allocations) ----------
__device__ float  g_At[NSTATE * NSTATE];    // g_At[n'*64 + n] = A[n][n']
__device__ float  g_w1[DD * NSTATE];        // [d][n] coeff of x  (mu * inv_var)
__device__ float  g_w2[DD * NSTATE];        // [d][n] coeff of x^2 (-0.5 * inv_var)
__device__ float  g_bias[NSTATE];
__device__ float  g_pi[NSTATE];
__device__ double g_chunk[BB * NCHUNK];     // per (b, chunk) contribution (incl. payload mB sum)

// ---------------- K0: prep (softmaxes + emission weights) ------------------
__global__ void k_prep(const float* __restrict__ tm, const float* __restrict__ priors,
                       const float* __restrict__ mu, const float* __restrict__ lv) {
    int n = threadIdx.x;  // 0..63
    float row[NSTATE];
    float m = -1e30f;
    #pragma unroll
    for (int j = 0; j < NSTATE; j++) { row[j] = tm[n * NSTATE + j]; m = fmaxf(m, row[j]); }
    float s = 0.f;
    #pragma unroll
    for (int j = 0; j < NSTATE; j++) { row[j] = expf(row[j] - m); s += row[j]; }
    float inv = 1.0f / s;
    #pragma unroll
    for (int j = 0; j < NSTATE; j++) g_At[j * NSTATE + n] = row[j] * inv;

    float pm = -1e30f;
    #pragma unroll
    for (int j = 0; j < NSTATE; j++) pm = fmaxf(pm, priors[j]);
    float ps = 0.f;
    #pragma unroll
    for (int j = 0; j < NSTATE; j++) ps += expf(priors[j] - pm);
    g_pi[n] = expf(priors[n] - pm) / ps;

    float slv = 0.f, smm = 0.f;
    #pragma unroll
    for (int d = 0; d < DD; d++) {
        float l  = lv[n * DD + d];
        float iv = expf(-l);
        float mu_ = mu[n * DD + d];
        g_w1[d * NSTATE + n] = mu_ * iv;
        g_w2[d * NSTATE + n] = -0.5f * iv;
        slv += l;
        smm += mu_ * mu_ * iv;
    }
    g_bias[n] = -0.5f * ((float)DD * LOG_2PI + slv) - 0.5f * smm;
}

// ---------------- K1: fused emission + chunked forward scan ----------------
// grid = (NCHUNK, BB), 128 threads. Chunk c covers global t in
// [128c-16, 128c+128); rows with t<0 (chunk 0 only) are zero-filled dummies.
// Phase A: compute p = exp(logB - rowmax) for all 144 rows into smem.
// Phase B: warps 0-1 run the scan over those rows; telescoping contribution
// (including this chunk's payload rowmax sum) is written to g_chunk.
__global__ void __launch_bounds__(128) k_fused(const float* __restrict__ X) {
    extern __shared__ float sm[];
    float* xs  = sm;                       // [64][XSTRIDE] X^T during phase A; then p [144][64]
    float* w1s = sm + 64 * XSTRIDE;        // [d][n]
    float* w2s = w1s + DD * NSTATE;

    __shared__ __align__(16) float vs[2][NSTATE];
    __shared__ float ubc_s;
    __shared__ float sredB[2], sredE[2];
    __shared__ float mred[4];

    const int c   = blockIdx.x;
    const int b   = blockIdx.y;
    const int tid = threadIdx.x;
    const int tx  = tid & 15;              // 4 states each
    const int ty  = tid >> 4;              // 0..7, row-pair group
    const int base = 128 * c - BURN;       // global t of local row 0

    // ---- load weights (8192 floats) ----
    #pragma unroll
    for (int q = 0; q < 8; q++) {
        int fid = tid + 128 * q;
        ((float4*)w1s)[fid] = ((const float4*)g_w1)[fid];
        ((float4*)w2s)[fid] = ((const float4*)g_w2)[fid];
    }
    // ---- load X slab (144 rows x 64 d), transposed; t<0 -> zeros ----
    #pragma unroll
    for (int q = 0; q < 18; q++) {
        int fid = tid + 128 * q;           // 0..2303
        int row = fid >> 4;
        int dg  = fid & 15;
        int t   = base + row;
        float4 v = make_float4(0.f, 0.f, 0.f, 0.f);
        if (t >= 0) v = ((const float4*)X)[((size_t)b * TLEN + t) * 16 + dg];
        xs[(4 * dg + 0) * XSTRIDE + row] = v.x;
        xs[(4 * dg + 1) * XSTRIDE + row] = v.y;
        xs[(4 * dg + 2) * XSTRIDE + row] = v.z;
        xs[(4 * dg + 3) * XSTRIDE + row] = v.w;
    }
    __syncthreads();

    // ---- Phase A: emission. 9 row-pairs x 4 states per thread.
    // f32x2 lanes = (even row, odd row); x pair loads are LDS.64, w broadcasts.
    uint64_t acc[9][4];
    #pragma unroll
    for (int m = 0; m < 9; m++)
        #pragma unroll
        for (int cc = 0; cc < 4; cc++) acc[m][cc] = 0ull;

    #pragma unroll 4
    for (int d = 0; d < DD; d++) {
        float4 w1v = *(const float4*)&w1s[d * 64 + 4 * tx];
        float4 w2v = *(const float4*)&w2s[d * 64 + 4 * tx];
        uint64_t wb1[4], wb2[4];
        BCAST2(wb1[0], w1v.x); BCAST2(wb1[1], w1v.y); BCAST2(wb1[2], w1v.z); BCAST2(wb1[3], w1v.w);
        BCAST2(wb2[0], w2v.x); BCAST2(wb2[1], w2v.y); BCAST2(wb2[2], w2v.z); BCAST2(wb2[3], w2v.w);
        #pragma unroll
        for (int m = 0; m < 9; m++) {
            uint64_t xp = *(const uint64_t*)&xs[d * XSTRIDE + 16 * m + 2 * ty];
            #pragma unroll
            for (int cc = 0; cc < 4; cc++) {
                uint64_t tpk;
                FFMA2_3(tpk, xp, wb2[cc], wb1[cc]);   // t = x*w2 + w1
                FFMA2_ACC(acc[m][cc], xp, tpk);       // acc += x*t
            }
        }
    }
    __syncthreads();   // all xs reads done; safe to overwrite with p

    // bias + row max + exp + store p; accumulate payload rowmax sum
    float4 bv = *(const float4*)&g_bias[4 * tx];
    float ba[4] = {bv.x, bv.y, bv.z, bv.w};
    float msum = 0.f;
    #pragma unroll
    for (int m = 0; m < 9; m++) {
        float ve[4], vo[4];
        #pragma unroll
        for (int cc = 0; cc < 4; cc++) {
            float lo, hi; UNPACK2(lo, hi, acc[m][cc]);
            ve[cc] = lo + ba[cc];
            vo[cc] = hi + ba[cc];
        }
        float me = fmaxf(fmaxf(ve[0], ve[1]), fmaxf(ve[2], ve[3]));
        float mo = fmaxf(fmaxf(vo[0], vo[1]), fmaxf(vo[2], vo[3]));
        #pragma unroll
        for (int off = 1; off < 16; off <<= 1) {
            me = fmaxf(me, __shfl_xor_sync(0xffffffffu, me, off));
            mo = fmaxf(mo, __shfl_xor_sync(0xffffffffu, mo, off));
        }
        int r0 = 16 * m + 2 * ty;
        float4 pe, po;
        pe.x = __expf(ve[0] - me); pe.y = __expf(ve[1] - me);
        pe.z = __expf(ve[2] - me); pe.w = __expf(ve[3] - me);
        po.x = __expf(vo[0] - mo); po.y = __expf(vo[1] - mo);
        po.z = __expf(vo[2] - mo); po.w = __expf(vo[3] - mo);
        *(float4*)&xs[r0 * 64 + 4 * tx]       = pe;    // p[row][n], reusing xs region
        *(float4*)&xs[(r0 + 1) * 64 + 4 * tx] = po;
        if (m >= 1 && tx == 0) msum += me + mo;        // m==0 rows are burn-in (or dummies)
    }
    msum += __shfl_xor_sync(0xffffffffu, msum, 16);
    if ((tid & 31) == 0) mred[tid >> 5] = msum;

    // ---- Phase B: scan (warps 0-1; warps 2-3 just run barriers) ----
    uint64_t a2[32];
    if (tid < 64) {
        const ulonglong2* at2 = (const ulonglong2*)(g_At + tid * NSTATE);
        #pragma unroll
        for (int q = 0; q < 16; q++) {
            ulonglong2 tq = at2[q];
            a2[2 * q] = tq.x; a2[2 * q + 1] = tq.y;
        }
    }
    const int n = tid;
    const int s_begin = (c == 0) ? (BURN + 1) : 0;
    float w = 0.f;
    __syncthreads();   // p + mred visible
    if (tid < 64) {
        w = (c == 0) ? (g_pi[n] * xs[BURN * 64 + n]) : 1.0f;
        vs[0][n] = w;
        if (n == 0) ubc_s = 1.0f;
    }
    __syncthreads();

    double lacc = 0.0, laccB = 0.0;
    int s = 0;
    for (int lr = s_begin; lr < ROWS; lr++) {
        if (tid < 64) {
            if (c > 0 && lr == BURN) {            // boundary snapshot: w = v after lr-1
                float r = w;
                #pragma unroll
                for (int off = 16; off; off >>= 1) r += __shfl_xor_sync(0xffffffffu, r, off);
                if ((n & 31) == 0) sredB[n >> 5] = r;
                laccB = lacc;
            }
            const int rb = s & 1, wbuf = rb ^ 1;
            uint64_t ac0 = 0ull, ac1 = 0ull, ac2 = 0ull, ac3 = 0ull;
            const ulonglong2* v2 = (const ulonglong2*)vs[rb];
            #pragma unroll
            for (int q = 0; q < 8; q++) {
                ulonglong2 va = v2[2 * q];
                ulonglong2 vb = v2[2 * q + 1];
                FFMA2_ACC(ac0, a2[4 * q + 0], va.x);
                FFMA2_ACC(ac1, a2[4 * q + 1], va.y);
                FFMA2_ACC(ac2, a2[4 * q + 2], vb.x);
                FFMA2_ACC(ac3, a2[4 * q + 3], vb.y);
            }
            uint64_t s01, s23, st;
            ADD2(s01, ac0, ac1);
            ADD2(s23, ac2, ac3);
            ADD2(st, s01, s23);
            float ulo, uhi; UNPACK2(ulo, uhi, st);
            float u = ulo + uhi;

            float scale = xs[lr * 64 + n];        // p from smem
            if (s > 0 && (s & 7) == 0) {          // rescale: ubc written at s&7==7 (prev epoch)
                float sc = ubc_s * 64.0f;
                scale *= (1.0f / sc);
                lacc += (double)logf(sc);
            }
            w = u * scale;
            vs[wbuf][n] = w;
            if (n == 0 && (s & 7) == 7) ubc_s = u;
        }
        s++;
        __syncthreads();
    }

    if (tid < 64) {
        float r = w;
        #pragma unroll
        for (int off = 16; off; off >>= 1) r += __shfl_xor_sync(0xffffffffu, r, off);
        if ((n & 31) == 0) sredE[n >> 5] = r;
    }
    __syncthreads();
    if (tid == 0) {
        double msumT = (double)(((mred[0] + mred[1]) + (mred[2] + mred[3])));
        double endv  = log((double)(sredE[0] + sredE[1])) + lacc;
        double bndv  = (c == 0) ? 0.0 : (log((double)(sredB[0] + sredB[1])) + laccB);
        g_chunk[b * NCHUNK + c] = endv - bndv + msumT;
    }
}

// ---------------- K2: deterministic final sum ------------------------------
__global__ void k_final(float* out) {
    __shared__ double part[BB];
    int b = threadIdx.x;   // 64 threads, one per batch
    double s = 0.0;
    #pragma unroll 16
    for (int cc = 0; cc < NCHUNK; cc++) s += g_chunk[b * NCHUNK + cc];
    part[b] = s;
    __syncthreads();
    if (b == 0) {
        double tot = 0.0;
        #pragma unroll
        for (int i = 0; i < BB; i++) tot += part[i];
        out[0] = (float)tot;
    }
}

// ---------------- launch ---------------------------------------------------
extern "C" void kernel_launch(void* const* d_in, const int* in_sizes, int n_in,
                              void* d_out, int out_size) {
    const float* X   = (const float*)d_in[0];
    const float* tm  = (const float*)d_in[1];
    const float* pri = (const float*)d_in[2];
    const float* mu  = (const float*)d_in[3];
    const float* lv  = (const float*)d_in[4];

    const int smem = (64 * XSTRIDE + 2 * DD * NSTATE) * 4;   // 70144 B
    cudaFuncSetAttribute(k_fused, cudaFuncAttributeMaxDynamicSharedMemorySize, smem);

    k_prep<<<1, 64>>>(tm, pri, mu, lv);
    dim3 fg(NCHUNK, BB);
    k_fused<<<fg, 128, smem>>>(X);
    k_final<<<1, BB>>>((float*)d_out);
}

// round 9
// speedup vs baseline: 1.0758x; 1.0758x over previous
#include <cuda_runtime.h>
#include <cuda_bf16.h>
#include <cstdint>

#define BB 64
#define TLEN 8192
#define DD 64
#define NSTATE 64
#define NCHUNK 64           // chunks per batch
#define CLEN 128            // payload transitions per chunk
#define BURN 16             // burn-in steps (direction recovery)

#define LOG_2PI 1.8378770664093453f

// ---- packed f32x2 helpers (Blackwell FFMA2 path; PTX-only) ----
#define FFMA2_ACC(d, a, b) asm("fma.rn.f32x2 %0, %1, %2, %0;" : "+l"(d) : "l"(a), "l"(b))
#define FFMA2_3(d, a, b, c) asm("fma.rn.f32x2 %0, %1, %2, %3;" : "=l"(d) : "l"(a), "l"(b), "l"(c))
#define ADD2(d, a, b)       asm("add.rn.f32x2 %0, %1, %2;" : "=l"(d) : "l"(a), "l"(b))
#define BCAST2(d, x)        asm("mov.b64 %0, {%1, %1};" : "=l"(d) : "f"(x))
#define UNPACK2(lo, hi, p)  asm("mov.b64 {%0, %1}, %2;" : "=f"(lo), "=f"(hi) : "l"(p))

// ---------------- scratch (static device globals; no allocations) ----------
__device__ float  g_p[(size_t)BB * TLEN * NSTATE + 1024]; // p = exp(logB - mB), padded for prefetch
__device__ float  g_A2[NSTATE * NSTATE];    // g_A2[m*64 + j] = A[j][m]  (dest-major, j-contiguous)
__device__ float  g_w1[DD * NSTATE];        // [d][n] coeff of x  (mu * inv_var)
__device__ float  g_w2[DD * NSTATE];        // [d][n] coeff of x^2 (-0.5 * inv_var)
__device__ float  g_bias[NSTATE];
__device__ float  g_pi[NSTATE];
__device__ float  g_mBpart[4096];           // per 128-row emission block: sum of row maxes
__device__ double g_chunk[BB * NCHUNK];     // per (b, chunk) log-mass contribution

// ---------------- K0: prep (softmaxes + emission weights) ------------------
__global__ void k_prep(const float* __restrict__ tm, const float* __restrict__ priors,
                       const float* __restrict__ mu, const float* __restrict__ lv) {
    int n = threadIdx.x;  // 0..63
    float row[NSTATE];
    float m = -1e30f;
    #pragma unroll
    for (int j = 0; j < NSTATE; j++) { row[j] = tm[n * NSTATE + j]; m = fmaxf(m, row[j]); }
    float s = 0.f;
    #pragma unroll
    for (int j = 0; j < NSTATE; j++) { row[j] = expf(row[j] - m); s += row[j]; }
    float inv = 1.0f / s;
    // row[m] = A[n][m]; dest-major layout: g_A2[m][j] = A[j][m]  -> g_A2[m*64 + n] = row[m]
    #pragma unroll
    for (int j = 0; j < NSTATE; j++) g_A2[j * NSTATE + n] = row[j] * inv;

    float pm = -1e30f;
    #pragma unroll
    for (int j = 0; j < NSTATE; j++) pm = fmaxf(pm, priors[j]);
    float ps = 0.f;
    #pragma unroll
    for (int j = 0; j < NSTATE; j++) ps += expf(priors[j] - pm);
    g_pi[n] = expf(priors[n] - pm) / ps;

    float slv = 0.f, smm = 0.f;
    #pragma unroll
    for (int d = 0; d < DD; d++) {
        float l  = lv[n * DD + d];
        float iv = expf(-l);
        float mu_ = mu[n * DD + d];
        g_w1[d * NSTATE + n] = mu_ * iv;
        g_w2[d * NSTATE + n] = -0.5f * iv;
        slv += l;
        smm += mu_ * mu_ * iv;
    }
    g_bias[n] = -0.5f * ((float)DD * LOG_2PI + slv) - 0.5f * smm;
}

// ---------------- K1: emission p + row-max, 128 rows x 64 states per CTA ---
__global__ void __launch_bounds__(256) k_emission(const float* __restrict__ X) {
    extern __shared__ float sm[];
    float* xs  = sm;           // [d][row] transposed
    float* w1s = sm + 8192;    // [d][n]
    float* w2s = sm + 12288;   // [d][n]

    const int tid = threadIdx.x;
    const int tx  = tid & 15;        // col group: 4 states
    const int ty  = tid >> 4;        // row group: 8 rows

    const float* Xb = X + (size_t)blockIdx.x * 128 * DD;
    const float4* Xg = (const float4*)Xb;
    #pragma unroll
    for (int q = 0; q < 8; q++) {
        int fid = tid + 256 * q;
        int row = fid & 127;
        int dg  = fid >> 7;
        float4 v = Xg[row * 16 + dg];
        xs[(4 * dg + 0) * 128 + row] = v.x;
        xs[(4 * dg + 1) * 128 + row] = v.y;
        xs[(4 * dg + 2) * 128 + row] = v.z;
        xs[(4 * dg + 3) * 128 + row] = v.w;
    }
    #pragma unroll
    for (int q = 0; q < 4; q++) {
        int fid = tid + 256 * q;
        ((float4*)w1s)[fid] = ((const float4*)g_w1)[fid];
        ((float4*)w2s)[fid] = ((const float4*)g_w2)[fid];
    }
    __syncthreads();

    uint64_t accp[8][2];
    #pragma unroll
    for (int r = 0; r < 8; r++) { accp[r][0] = 0ull; accp[r][1] = 0ull; }

    #pragma unroll 4
    for (int d = 0; d < DD; d++) {
        const float4* xp = (const float4*)&xs[d * 128 + 8 * ty];
        float4 x0 = xp[0];
        float4 x1 = xp[1];
        ulonglong2 w1v = *(const ulonglong2*)&w1s[d * 64 + 4 * tx];
        ulonglong2 w2v = *(const ulonglong2*)&w2s[d * 64 + 4 * tx];
        float xr[8] = {x0.x, x0.y, x0.z, x0.w, x1.x, x1.y, x1.z, x1.w};
        #pragma unroll
        for (int r = 0; r < 8; r++) {
            uint64_t xb; BCAST2(xb, xr[r]);
            uint64_t t0, t1;
            FFMA2_3(t0, xb, w2v.x, w1v.x);
            FFMA2_3(t1, xb, w2v.y, w1v.y);
            FFMA2_ACC(accp[r][0], xb, t0);
            FFMA2_ACC(accp[r][1], xb, t1);
        }
    }
    float acc[8][4];
    #pragma unroll
    for (int r = 0; r < 8; r++) {
        UNPACK2(acc[r][0], acc[r][1], accp[r][0]);
        UNPACK2(acc[r][2], acc[r][3], accp[r][1]);
    }
    __syncthreads();

    float* red  = sm;          // [128][16]
    float* mrow = sm + 2048;   // [128]
    float* wsum = sm + 2176;   // [4]

    float4 bv = *(const float4*)&g_bias[4 * tx];
    float ba[4] = {bv.x, bv.y, bv.z, bv.w};
    #pragma unroll
    for (int r = 0; r < 8; r++) {
        float mx = -1e30f;
        #pragma unroll
        for (int c = 0; c < 4; c++) {
            acc[r][c] += ba[c];
            mx = fmaxf(mx, acc[r][c]);
        }
        red[(8 * ty + r) * 16 + tx] = mx;
    }
    __syncthreads();

    float m = 0.f;
    if (tid < 128) {
        int row = tid;
        m = red[row * 16];
        #pragma unroll
        for (int k = 1; k < 16; k++) m = fmaxf(m, red[row * 16 + k]);
        mrow[row] = m;
    }
    __syncthreads();

    const size_t baseRow = (size_t)blockIdx.x * 128;
    #pragma unroll
    for (int r = 0; r < 8; r++) {
        float mr = mrow[8 * ty + r];
        float4 p4;
        p4.x = __expf(acc[r][0] - mr);
        p4.y = __expf(acc[r][1] - mr);
        p4.z = __expf(acc[r][2] - mr);
        p4.w = __expf(acc[r][3] - mr);
        *(float4*)&g_p[(baseRow + 8 * ty + r) * NSTATE + 4 * tx] = p4;
    }

    if (tid < 128) {
        float rs = m;
        #pragma unroll
        for (int off = 16; off; off >>= 1) rs += __shfl_xor_sync(0xffffffffu, rs, off);
        if ((tid & 31) == 0) wsum[tid >> 5] = rs;
    }
    __syncthreads();
    if (tid == 0) g_mBpart[blockIdx.x] = (wsum[0] + wsum[1]) + (wsum[2] + wsum[3]);
}

// ---------------- K2: warp-synchronous chunked forward scan ----------------
// One WARP per (batch, chunk) chain; lane l owns states 2l, 2l+1.
// A held in 128 regs as j-packed f32x2 pairs; v in per-warp smem ping-pong;
// no __syncthreads anywhere — only __syncwarp.
__global__ void __launch_bounds__(128) k_scan() {
    const int wid = threadIdx.x >> 5;
    const int l   = threadIdx.x & 31;
    const int chain = blockIdx.x * 4 + wid;
    const int b = chain >> 6;           // / NCHUNK
    const int c = chain & (NCHUNK - 1);

    __shared__ __align__(16) float vbuf[4][2][NSTATE];

    const int n0 = 2 * l, n1 = 2 * l + 1;

    // A rows for states n0, n1: a?[j] = (A[2j][n], A[2j+1][n]), contiguous in g_A2
    uint64_t a0[32], a1[32];
    {
        const uint64_t* r0 = (const uint64_t*)(g_A2 + n0 * NSTATE);
        const uint64_t* r1 = (const uint64_t*)(g_A2 + n1 * NSTATE);
        #pragma unroll
        for (int j = 0; j < 32; j++) { a0[j] = r0[j]; a1[j] = r1[j]; }
    }

    const float* pb = g_p + (size_t)b * TLEN * NSTATE;

    const int t0 = (c == 0) ? 1 : (CLEN * c - BURN);
    const int t1 = CLEN * c + CLEN;     // exclusive
    const int tb = CLEN * c;            // boundary snapshot (c>0)

    float w0, w1;
    if (c == 0) {
        float2 pi2 = *(const float2*)(g_pi + n0);
        float2 pp  = *(const float2*)(pb + n0);
        w0 = pi2.x * pp.x;
        w1 = pi2.y * pp.y;
    } else {
        w0 = 1.0f; w1 = 1.0f;
    }
    *(float2*)&vbuf[wid][0][n0] = make_float2(w0, w1);

    // p prefetch ring, depth 8 (pairs)
    uint64_t pbuf[8];
    #pragma unroll
    for (int i = 0; i < 8; i++)
        pbuf[i] = *(const uint64_t*)(pb + (size_t)(t0 + i) * NSTATE + n0);
    __syncwarp();

    double lacc = 0.0, laccB = 0.0;
    float bsum = 1.0f;
    float prev_u0 = 1.0f;
    int ring = 0;

    for (int t = t0; t < t1; ++t) {
        const int s  = t - t0;
        const int rb = s & 1;

        if (c > 0 && t == tb) {          // snapshot: (w0,w1) = v after step t-1
            float r = w0 + w1;
            #pragma unroll
            for (int off = 16; off; off >>= 1) r += __shfl_xor_sync(0xffffffffu, r, off);
            bsum = r;
            laccB = lacc;
        }

        uint64_t x0 = 0ull, x1 = 0ull, y0 = 0ull, y1 = 0ull;
        const ulonglong2* v2 = (const ulonglong2*)&vbuf[wid][rb][0];
        #pragma unroll
        for (int q = 0; q < 16; q++) {
            ulonglong2 vq = v2[q];       // (v[4q],v[4q+1]) , (v[4q+2],v[4q+3])
            FFMA2_ACC(x0, a0[2 * q],     vq.x);
            FFMA2_ACC(x1, a0[2 * q + 1], vq.y);
            FFMA2_ACC(y0, a1[2 * q],     vq.x);
            FFMA2_ACC(y1, a1[2 * q + 1], vq.y);
        }
        uint64_t sx, sy;
        ADD2(sx, x0, x1);
        ADD2(sy, y0, y1);
        float e0, o0, e1, o1;
        UNPACK2(e0, o0, sx);
        UNPACK2(e1, o1, sy);
        float u0 = e0 + o0;
        float u1 = e1 + o1;

        uint64_t ppk = pbuf[ring];
        pbuf[ring] = *(const uint64_t*)(pb + (size_t)(t + 8) * NSTATE + n0); // padded
        ring = (ring + 1) & 7;
        float p0, p1; UNPACK2(p0, p1, ppk);

        if (s > 0 && (s & 7) == 0) {     // rescale (factor from previous step, lane 0)
            float su = __shfl_sync(0xffffffffu, prev_u0, 0) * 64.0f;
            float im = 1.0f / su;
            p0 *= im; p1 *= im;
            lacc += (double)logf(su);
        }
        w0 = u0 * p0;
        w1 = u1 * p1;
        prev_u0 = u0;

        *(float2*)&vbuf[wid][rb ^ 1][n0] = make_float2(w0, w1);
        __syncwarp();
    }

    // final reduction of v_{t1-1}
    float r = w0 + w1;
    #pragma unroll
    for (int off = 16; off; off >>= 1) r += __shfl_xor_sync(0xffffffffu, r, off);
    if (l == 0) {
        double endv = log((double)r) + lacc;
        double bndv = (c == 0) ? 0.0 : (log((double)bsum) + laccB);
        g_chunk[b * NCHUNK + c] = endv - bndv;
    }
}

// ---------------- K3: deterministic final sum ------------------------------
__global__ void k_final(float* out) {
    __shared__ double part[BB];
    int b = threadIdx.x;   // 64 threads, one per batch
    double s = 0.0;
    #pragma unroll 16
    for (int cc = 0; cc < NCHUNK; cc++) s += g_chunk[b * NCHUNK + cc];
    float ms = 0.f;
    #pragma unroll 8
    for (int i = 0; i < 64; i++) ms += g_mBpart[b * 64 + i];
    part[b] = s + (double)ms;
    __syncthreads();
    if (b == 0) {
        double tot = 0.0;
        #pragma unroll
        for (int i = 0; i < BB; i++) tot += part[i];
        out[0] = (float)tot;
    }
}

// ---------------- launch ---------------------------------------------------
extern "C" void kernel_launch(void* const* d_in, const int* in_sizes, int n_in,
                              void* d_out, int out_size) {
    const float* X   = (const float*)d_in[0];
    const float* tm  = (const float*)d_in[1];
    const float* pri = (const float*)d_in[2];
    const float* mu  = (const float*)d_in[3];
    const float* lv  = (const float*)d_in[4];

    cudaFuncSetAttribute(k_emission, cudaFuncAttributeMaxDynamicSharedMemorySize, 65536);

    k_prep<<<1, 64>>>(tm, pri, mu, lv);
    k_emission<<<4096, 256, 65536>>>(X);
    k_scan<<<(BB * NCHUNK) / 4, 128>>>();
    k_final<<<1, BB>>>((float*)d_out);
}

// round 11
// speedup vs baseline: 1.5440x; 1.4352x over previous
#include <cuda_runtime.h>
#include <cuda_bf16.h>
#include <cstdint>

#define BB 64
#define TLEN 8192
#define DD 64
#define NSTATE 64
#define NCHUNK 128          // chunks per batch (scan)
#define CLEN 64             // payload transitions per chunk
#define BURN 16             // burn-in steps

#define LOG_2PI 1.8378770664093453f

// ---- packed f32x2 helpers (scan only) ----
#define FFMA2_ACC(d, a, b) asm("fma.rn.f32x2 %0, %1, %2, %0;" : "+l"(d) : "l"(a), "l"(b))
#define ADD2(d, a, b)       asm("add.rn.f32x2 %0, %1, %2;" : "=l"(d) : "l"(a), "l"(b))
#define UNPACK2(lo, hi, p)  asm("mov.b64 {%0, %1}, %2;" : "=f"(lo), "=f"(hi) : "l"(p))

__device__ __forceinline__ uint32_t smem_u32(const void* p) {
    uint32_t a;
    asm("{ .reg .u64 t; cvta.to.shared.u64 t, %1; cvt.u32.u64 %0, t; }" : "=r"(a) : "l"(p));
    return a;
}

__device__ __forceinline__ uint32_t bfpack(float lo, float hi) {
    __nv_bfloat162 h = __floats2bfloat162_rn(lo, hi);
    uint32_t u;
    memcpy(&u, &h, 4);
    return u;
}

// ---------------- scratch (static device globals; no allocations) ----------
__device__ float    g_p[(size_t)BB * TLEN * NSTATE + 1024];
__device__ float    g_At[NSTATE * NSTATE];       // scan layout: g_At[j*64+n] = A[n][j]
__device__ uint32_t g_Bfrag[8][8][32][2];        // [kstep][ntile][lane][reg] bf16x2 B fragments
__device__ float    g_bias[NSTATE];
__device__ float    g_pi[NSTATE];
__device__ float    g_mBpart[4096];
__device__ double   g_chunk[BB * NCHUNK];

// ---------------- K0: prep ------------------------------------------------
__global__ void k_prep(const float* __restrict__ tm, const float* __restrict__ priors,
                       const float* __restrict__ mu, const float* __restrict__ lv) {
    int n = threadIdx.x;  // 0..63
    float row[NSTATE];
    float m = -1e30f;
    #pragma unroll
    for (int j = 0; j < NSTATE; j++) { row[j] = tm[n * NSTATE + j]; m = fmaxf(m, row[j]); }
    float s = 0.f;
    #pragma unroll
    for (int j = 0; j < NSTATE; j++) { row[j] = expf(row[j] - m); s += row[j]; }
    float inv = 1.0f / s;
    #pragma unroll
    for (int j = 0; j < NSTATE; j++) g_At[j * NSTATE + n] = row[j] * inv;

    float pm = -1e30f;
    #pragma unroll
    for (int j = 0; j < NSTATE; j++) pm = fmaxf(pm, priors[j]);
    float ps = 0.f;
    #pragma unroll
    for (int j = 0; j < NSTATE; j++) ps += expf(priors[j] - pm);
    g_pi[n] = expf(priors[n] - pm) / ps;

    float w1a[DD], w2a[DD];
    float slv = 0.f, smm = 0.f;
    #pragma unroll
    for (int d = 0; d < DD; d++) {
        float l  = lv[n * DD + d];
        float iv = expf(-l);
        float mu_ = mu[n * DD + d];
        w1a[d] = mu_ * iv;          // coeff of x_d   (feature col d)
        w2a[d] = -0.5f * iv;        // coeff of x_d^2 (feature col 64+d)
        slv += l;
        smm += mu_ * mu_ * iv;
    }
    g_bias[n] = -0.5f * ((float)DD * LOG_2PI + slv) - 0.5f * smm;

    // B fragments for mma.m16n8k16.row.col: thread lane holds
    //   b0 = (k = (lane%4)*2 + {0,1}, col n = lane/4)
    //   b1 = same with k+8
    // Our B is W[n][k] (col-major of k x n): W[n][k] = k<64 ? w1a[k] : w2a[k-64]
    const int nt = n >> 3;
    const int g  = n & 7;
    #pragma unroll
    for (int t = 0; t < 4; t++) {
        int lane = g * 4 + t;
        #pragma unroll
        for (int ks = 0; ks < 8; ks++) {
            #pragma unroll
            for (int r = 0; r < 2; r++) {
                int k = ks * 16 + t * 2 + r * 8;
                float v0 = (k < 64) ? w1a[k] : w2a[k - 64];
                float v1 = (k + 1 < 64) ? w1a[k + 1] : w2a[k + 1 - 64];
                g_Bfrag[ks][nt][lane][r] = bfpack(v0, v1);
            }
        }
    }
}

// ---------------- K1: HMMA emission ----------------------------------------
// One CTA (128 thr = 4 warps) per 128-row tile; warp w owns rows 32w..32w+31.
__global__ void __launch_bounds__(128) k_emission(const float* __restrict__ X) {
    __shared__ __align__(16) __nv_bfloat16 feat[128][136];   // padded stride
    __shared__ float s_wred[4];

    const int tid  = threadIdx.x;
    const int wid  = tid >> 5;
    const int lane = tid & 31;

    // ---- load X tile -> bf16 feat = [x | x^2] ----
    #pragma unroll
    for (int q = 0; q < 16; q++) {
        int fid = tid + 128 * q;          // 0..2047
        int row = fid >> 4;
        int dg  = fid & 15;
        float4 v = ((const float4*)X)[((size_t)blockIdx.x * 128 + row) * 16 + dg];
        uint32_t x01 = bfpack(v.x, v.y);
        uint32_t x23 = bfpack(v.z, v.w);
        uint32_t s01 = bfpack(v.x * v.x, v.y * v.y);
        uint32_t s23 = bfpack(v.z * v.z, v.w * v.w);
        *(uint2*)&feat[row][4 * dg]      = make_uint2(x01, x23);
        *(uint2*)&feat[row][64 + 4 * dg] = make_uint2(s01, s23);
    }
    __syncthreads();

    // ---- MMA mainloop: acc[mt][nt][4], mt = 16-row halves of the warp's 32 rows
    float acc[2][8][4];
    #pragma unroll
    for (int mt = 0; mt < 2; mt++)
        #pragma unroll
        for (int nt = 0; nt < 8; nt++)
            #pragma unroll
            for (int r = 0; r < 4; r++) acc[mt][nt][r] = 0.f;

    const int warpbase = wid * 32;
    #pragma unroll
    for (int ks = 0; ks < 8; ks++) {
        uint32_t a[2][4];
        #pragma unroll
        for (int mt = 0; mt < 2; mt++) {
            int row = warpbase + mt * 16 + (lane & 15);
            int col = ks * 16 + (lane >> 4) * 8;
            uint32_t addr = smem_u32(&feat[row][col]);
            asm volatile("ldmatrix.sync.aligned.m8n8.x4.shared.b16 {%0,%1,%2,%3}, [%4];"
                         : "=r"(a[mt][0]), "=r"(a[mt][1]), "=r"(a[mt][2]), "=r"(a[mt][3])
                         : "r"(addr));
        }
        #pragma unroll
        for (int nt = 0; nt < 8; nt++) {
            uint2 b = *(const uint2*)&g_Bfrag[ks][nt][lane][0];
            #pragma unroll
            for (int mt = 0; mt < 2; mt++) {
                asm volatile(
                    "mma.sync.aligned.m16n8k16.row.col.f32.bf16.bf16.f32 "
                    "{%0,%1,%2,%3}, {%4,%5,%6,%7}, {%8,%9}, {%0,%1,%2,%3};"
                    : "+f"(acc[mt][nt][0]), "+f"(acc[mt][nt][1]),
                      "+f"(acc[mt][nt][2]), "+f"(acc[mt][nt][3])
                    : "r"(a[mt][0]), "r"(a[mt][1]), "r"(a[mt][2]), "r"(a[mt][3]),
                      "r"(b.x), "r"(b.y));
            }
        }
    }

    // ---- epilogue: bias, row max (4 lanes share a row), exp, store p ----
    float2 bload[8];
    #pragma unroll
    for (int nt = 0; nt < 8; nt++)
        bload[nt] = *(const float2*)&g_bias[nt * 8 + (lane & 3) * 2];

    float rm[4];
    #pragma unroll
    for (int mt = 0; mt < 2; mt++) {
        float m01 = -1e30f, m23 = -1e30f;
        #pragma unroll
        for (int nt = 0; nt < 8; nt++) {
            acc[mt][nt][0] += bload[nt].x;
            acc[mt][nt][1] += bload[nt].y;
            acc[mt][nt][2] += bload[nt].x;
            acc[mt][nt][3] += bload[nt].y;
            m01 = fmaxf(m01, fmaxf(acc[mt][nt][0], acc[mt][nt][1]));
            m23 = fmaxf(m23, fmaxf(acc[mt][nt][2], acc[mt][nt][3]));
        }
        rm[mt * 2 + 0] = m01;
        rm[mt * 2 + 1] = m23;
    }
    #pragma unroll
    for (int j = 0; j < 4; j++) {
        rm[j] = fmaxf(rm[j], __shfl_xor_sync(0xffffffffu, rm[j], 1));
        rm[j] = fmaxf(rm[j], __shfl_xor_sync(0xffffffffu, rm[j], 2));
    }

    const size_t R0 = (size_t)blockIdx.x * 128 + warpbase + (lane >> 2);
    #pragma unroll
    for (int mt = 0; mt < 2; mt++) {
        #pragma unroll
        for (int dp = 0; dp < 2; dp++) {
            const size_t row = R0 + mt * 16 + dp * 8;
            const float mr = rm[mt * 2 + dp];
            float* base = &g_p[row * NSTATE + (lane & 3) * 2];
            #pragma unroll
            for (int nt = 0; nt < 8; nt++) {
                float2 e;
                e.x = __expf(acc[mt][nt][2 * dp + 0] - mr);
                e.y = __expf(acc[mt][nt][2 * dp + 1] - mr);
                *(float2*)(base + nt * 8) = e;
            }
        }
    }

    // sum of the 128 row maxes of this tile (one contributor per row)
    float s = ((lane & 3) == 0) ? (rm[0] + rm[1]) + (rm[2] + rm[3]) : 0.f;
    #pragma unroll
    for (int off = 16; off; off >>= 1) s += __shfl_xor_sync(0xffffffffu, s, off);
    if (lane == 0) s_wred[wid] = s;
    __syncthreads();
    if (tid == 0)
        g_mBpart[blockIdx.x] = (s_wred[0] + s_wred[1]) + (s_wred[2] + s_wred[3]);
}

// ---------------- K2: chunked forward scan (R5 version, best measured) -----
__global__ void __launch_bounds__(64) k_scan() {
    const int c = blockIdx.x;
    const int b = blockIdx.y;
    const int n = threadIdx.x;

    __shared__ __align__(16) float vs[2][NSTATE];
    __shared__ float ubc;
    __shared__ float sredB[2];
    __shared__ float sredE[2];

    uint64_t a2[32];
    const ulonglong2* at2 = (const ulonglong2*)(g_At + n * NSTATE);
    #pragma unroll
    for (int q = 0; q < 16; q++) {
        ulonglong2 t = at2[q];
        a2[2 * q] = t.x; a2[2 * q + 1] = t.y;
    }

    const float* pb = g_p + (size_t)b * TLEN * NSTATE;

    const int t0 = (c == 0) ? 1 : (CLEN * c - BURN);
    const int t1 = CLEN * c + CLEN;
    const int tb = (c == 0) ? -1 : (CLEN * c);

    float w = (c == 0) ? (g_pi[n] * pb[n]) : 1.0f;
    vs[0][n] = w;
    if (n == 0) ubc = 1.0f;

    float pbuf[4];
    #pragma unroll
    for (int i = 0; i < 4; i++) pbuf[i] = pb[(size_t)(t0 + i) * NSTATE + n];
    __syncthreads();

    double lacc = 0.0, laccB = 0.0;
    int ring = 0;

    for (int t = t0; t < t1; ++t) {
        const int step = t - t0;
        const int rb = step & 1;
        const int wb = rb ^ 1;

        if (t == tb) {
            float r = w;
            #pragma unroll
            for (int off = 16; off; off >>= 1) r += __shfl_xor_sync(0xffffffffu, r, off);
            if ((n & 31) == 0) sredB[n >> 5] = r;
            laccB = lacc;
        }

        uint64_t acc0 = 0ull, acc1 = 0ull, acc2 = 0ull, acc3 = 0ull;
        const ulonglong2* v2 = (const ulonglong2*)vs[rb];
        #pragma unroll
        for (int q = 0; q < 8; q++) {
            ulonglong2 va  = v2[2 * q];
            ulonglong2 vb4 = v2[2 * q + 1];
            FFMA2_ACC(acc0, a2[4 * q + 0], va.x);
            FFMA2_ACC(acc1, a2[4 * q + 1], va.y);
            FFMA2_ACC(acc2, a2[4 * q + 2], vb4.x);
            FFMA2_ACC(acc3, a2[4 * q + 3], vb4.y);
        }
        uint64_t s01, s23, st;
        ADD2(s01, acc0, acc1);
        ADD2(s23, acc2, acc3);
        ADD2(st, s01, s23);
        float ulo, uhi; UNPACK2(ulo, uhi, st);
        float u = ulo + uhi;

        float scale = pbuf[ring];
        pbuf[ring] = pb[(size_t)(t + 4) * NSTATE + n];
        ring = (ring + 1) & 3;

        if ((step & 7) == 0 && step != 0) {
            float s = ubc * 64.0f;
            scale *= (1.0f / s);
            lacc += (double)logf(s);
        }
        w = u * scale;
        vs[wb][n] = w;
        if (n == 0) ubc = u;
        __syncthreads();
    }

    {
        float r = w;
        #pragma unroll
        for (int off = 16; off; off >>= 1) r += __shfl_xor_sync(0xffffffffu, r, off);
        if ((n & 31) == 0) sredE[n >> 5] = r;
    }
    __syncthreads();
    if (n == 0) {
        double endv = log((double)(sredE[0] + sredE[1])) + lacc;
        double bndv = (c == 0) ? 0.0 : (log((double)(sredB[0] + sredB[1])) + laccB);
        g_chunk[b * NCHUNK + c] = endv - bndv;
    }
}

// ---------------- K3: deterministic final sum ------------------------------
__global__ void k_final(float* out) {
    __shared__ double part[BB];
    int b = threadIdx.x;
    double s = 0.0;
    #pragma unroll 16
    for (int cc = 0; cc < NCHUNK; cc++) s += g_chunk[b * NCHUNK + cc];
    float ms = 0.f;
    #pragma unroll 8
    for (int i = 0; i < 64; i++) ms += g_mBpart[b * 64 + i];
    part[b] = s + (double)ms;
    __syncthreads();
    if (b == 0) {
        double tot = 0.0;
        #pragma unroll
        for (int i = 0; i < BB; i++) tot += part[i];
        out[0] = (float)tot;
    }
}

// ---------------- launch ---------------------------------------------------
extern "C" void kernel_launch(void* const* d_in, const int* in_sizes, int n_in,
                              void* d_out, int out_size) {
    const float* X   = (const float*)d_in[0];
    const float* tm  = (const float*)d_in[1];
    const float* pri = (const float*)d_in[2];
    const float* mu  = (const float*)d_in[3];
    const float* lv  = (const float*)d_in[4];

    k_prep<<<1, 64>>>(tm, pri, mu, lv);
    k_emission<<<4096, 128>>>(X);
    dim3 sg(NCHUNK, BB);
    k_scan<<<sg, NSTATE>>>();
    k_final<<<1, BB>>>((float*)d_out);
}

// round 12
// speedup vs baseline: 3.8054x; 2.4646x over previous
#include <cuda_runtime.h>
#include <cuda_bf16.h>
#include <cstdint>

#define BB 64
#define TLEN 8192
#define DD 64
#define NSTATE 64
#define NCHUNK 128          // chunks per batch (scan)
#define CLEN 64             // payload transitions per chunk
#define BURN 16             // burn-in steps

#define LOG_2PI 1.8378770664093453f

__device__ __forceinline__ uint32_t smem_u32(const void* p) {
    uint32_t a;
    asm("{ .reg .u64 t; cvta.to.shared.u64 t, %1; cvt.u32.u64 %0, t; }" : "=r"(a) : "l"(p));
    return a;
}

__device__ __forceinline__ uint32_t bfpack(float lo, float hi) {
    __nv_bfloat162 h = __floats2bfloat162_rn(lo, hi);
    uint32_t u;
    memcpy(&u, &h, 4);
    return u;
}

__device__ __forceinline__ float2 bfunpack(uint32_t u) {
    __nv_bfloat162 h;
    memcpy(&h, &u, 4);
    return __bfloat1622float2(h);
}

// ---------------- scratch (static device globals; no allocations) ----------
__device__ __align__(16) __nv_bfloat16 g_pT[(size_t)TLEN * BB * NSTATE + 16384]; // p_T[t][b][n], bf16
__device__ float    g_At[NSTATE * NSTATE];       // g_At[x*64+k] = A[k][x] (A-transpose staging)
__device__ uint32_t g_Bfrag[8][8][32][2];        // emission W fragments [ks][nt][lane][r]
__device__ uint32_t g_Afrag[4][8][32][2];        // scan A fragments     [ks][nt][lane][r]
__device__ float    g_bias[NSTATE];
__device__ float    g_pi[NSTATE];
__device__ float    g_mBpart[4096];
__device__ double   g_chunk[BB * NCHUNK];

// ---------------- K0: prep ------------------------------------------------
__global__ void k_prep(const float* __restrict__ tm, const float* __restrict__ priors,
                       const float* __restrict__ mu, const float* __restrict__ lv) {
    int n = threadIdx.x;  // 0..63
    float row[NSTATE];
    float m = -1e30f;
    #pragma unroll
    for (int j = 0; j < NSTATE; j++) { row[j] = tm[n * NSTATE + j]; m = fmaxf(m, row[j]); }
    float s = 0.f;
    #pragma unroll
    for (int j = 0; j < NSTATE; j++) { row[j] = expf(row[j] - m); s += row[j]; }
    float inv = 1.0f / s;
    // g_At[x*64+k] = A[k][x]; thread n contributes A[n][j] at g_At[j*64+n]
    #pragma unroll
    for (int j = 0; j < NSTATE; j++) g_At[j * NSTATE + n] = row[j] * inv;

    float pm = -1e30f;
    #pragma unroll
    for (int j = 0; j < NSTATE; j++) pm = fmaxf(pm, priors[j]);
    float ps = 0.f;
    #pragma unroll
    for (int j = 0; j < NSTATE; j++) ps += expf(priors[j] - pm);
    g_pi[n] = expf(priors[n] - pm) / ps;

    float w1a[DD], w2a[DD];
    float slv = 0.f, smm = 0.f;
    #pragma unroll
    for (int d = 0; d < DD; d++) {
        float l  = lv[n * DD + d];
        float iv = expf(-l);
        float mu_ = mu[n * DD + d];
        w1a[d] = mu_ * iv;
        w2a[d] = -0.5f * iv;
        slv += l;
        smm += mu_ * mu_ * iv;
    }
    g_bias[n] = -0.5f * ((float)DD * LOG_2PI + slv) - 0.5f * smm;

    // emission B fragments: B[k][col=n] = W[n][k]
    {
        const int nt = n >> 3;
        const int g  = n & 7;
        #pragma unroll
        for (int t = 0; t < 4; t++) {
            int lane = g * 4 + t;
            #pragma unroll
            for (int ks = 0; ks < 8; ks++) {
                #pragma unroll
                for (int r = 0; r < 2; r++) {
                    int k = ks * 16 + t * 2 + r * 8;
                    float v0 = (k < 64) ? w1a[k] : w2a[k - 64];
                    float v1 = (k + 1 < 64) ? w1a[k + 1] : w2a[k + 1 - 64];
                    g_Bfrag[ks][nt][lane][r] = bfpack(v0, v1);
                }
            }
        }
    }
    __syncthreads();
    // scan A fragments: B[k][col=n] = A[k][n] = g_At[n*64+k]
    {
        const int nt = n >> 3;
        const int g  = n & 7;
        const float* arow = &g_At[n * NSTATE];
        #pragma unroll
        for (int t = 0; t < 4; t++) {
            int lane = g * 4 + t;
            #pragma unroll
            for (int ks = 0; ks < 4; ks++) {
                #pragma unroll
                for (int r = 0; r < 2; r++) {
                    int k = ks * 16 + t * 2 + r * 8;
                    g_Afrag[ks][nt][lane][r] = bfpack(arow[k], arow[k + 1]);
                }
            }
        }
    }
}

// ---------------- K1: HMMA emission, writes transposed bf16 p --------------
// One CTA (128 thr = 4 warps) per 128-row (b,t) tile.
__global__ void __launch_bounds__(128) k_emission(const float* __restrict__ X) {
    __shared__ __align__(16) __nv_bfloat16 feat[128][136];
    __shared__ float s_wred[4];

    const int tid  = threadIdx.x;
    const int wid  = tid >> 5;
    const int lane = tid & 31;

    #pragma unroll
    for (int q = 0; q < 16; q++) {
        int fid = tid + 128 * q;
        int row = fid >> 4;
        int dg  = fid & 15;
        float4 v = ((const float4*)X)[((size_t)blockIdx.x * 128 + row) * 16 + dg];
        uint32_t x01 = bfpack(v.x, v.y);
        uint32_t x23 = bfpack(v.z, v.w);
        uint32_t s01 = bfpack(v.x * v.x, v.y * v.y);
        uint32_t s23 = bfpack(v.z * v.z, v.w * v.w);
        *(uint2*)&feat[row][4 * dg]      = make_uint2(x01, x23);
        *(uint2*)&feat[row][64 + 4 * dg] = make_uint2(s01, s23);
    }
    __syncthreads();

    float acc[2][8][4];
    #pragma unroll
    for (int mt = 0; mt < 2; mt++)
        #pragma unroll
        for (int nt = 0; nt < 8; nt++)
            #pragma unroll
            for (int r = 0; r < 4; r++) acc[mt][nt][r] = 0.f;

    const int warpbase = wid * 32;
    #pragma unroll
    for (int ks = 0; ks < 8; ks++) {
        uint32_t a[2][4];
        #pragma unroll
        for (int mt = 0; mt < 2; mt++) {
            int row = warpbase + mt * 16 + (lane & 15);
            int col = ks * 16 + (lane >> 4) * 8;
            uint32_t addr = smem_u32(&feat[row][col]);
            asm volatile("ldmatrix.sync.aligned.m8n8.x4.shared.b16 {%0,%1,%2,%3}, [%4];"
                         : "=r"(a[mt][0]), "=r"(a[mt][1]), "=r"(a[mt][2]), "=r"(a[mt][3])
                         : "r"(addr));
        }
        #pragma unroll
        for (int nt = 0; nt < 8; nt++) {
            uint2 b = *(const uint2*)&g_Bfrag[ks][nt][lane][0];
            #pragma unroll
            for (int mt = 0; mt < 2; mt++) {
                asm volatile(
                    "mma.sync.aligned.m16n8k16.row.col.f32.bf16.bf16.f32 "
                    "{%0,%1,%2,%3}, {%4,%5,%6,%7}, {%8,%9}, {%0,%1,%2,%3};"
                    : "+f"(acc[mt][nt][0]), "+f"(acc[mt][nt][1]),
                      "+f"(acc[mt][nt][2]), "+f"(acc[mt][nt][3])
                    : "r"(a[mt][0]), "r"(a[mt][1]), "r"(a[mt][2]), "r"(a[mt][3]),
                      "r"(b.x), "r"(b.y));
            }
        }
    }

    float2 bload[8];
    #pragma unroll
    for (int nt = 0; nt < 8; nt++)
        bload[nt] = *(const float2*)&g_bias[nt * 8 + (lane & 3) * 2];

    float rm[4];
    #pragma unroll
    for (int mt = 0; mt < 2; mt++) {
        float m01 = -1e30f, m23 = -1e30f;
        #pragma unroll
        for (int nt = 0; nt < 8; nt++) {
            acc[mt][nt][0] += bload[nt].x;
            acc[mt][nt][1] += bload[nt].y;
            acc[mt][nt][2] += bload[nt].x;
            acc[mt][nt][3] += bload[nt].y;
            m01 = fmaxf(m01, fmaxf(acc[mt][nt][0], acc[mt][nt][1]));
            m23 = fmaxf(m23, fmaxf(acc[mt][nt][2], acc[mt][nt][3]));
        }
        rm[mt * 2 + 0] = m01;
        rm[mt * 2 + 1] = m23;
    }
    #pragma unroll
    for (int j = 0; j < 4; j++) {
        rm[j] = fmaxf(rm[j], __shfl_xor_sync(0xffffffffu, rm[j], 1));
        rm[j] = fmaxf(rm[j], __shfl_xor_sync(0xffffffffu, rm[j], 2));
    }

    // transposed bf16 store: p_T[t][b][n]
    const int b    = blockIdx.x >> 6;
    const int toff = (blockIdx.x & 63) * 128;
    #pragma unroll
    for (int mt = 0; mt < 2; mt++) {
        #pragma unroll
        for (int dp = 0; dp < 2; dp++) {
            const int rloc = warpbase + (lane >> 2) + mt * 16 + dp * 8;
            const size_t t = (size_t)(toff + rloc);
            const float mr = rm[mt * 2 + dp];
            __nv_bfloat16* base = &g_pT[(t * 64 + b) * 64 + (lane & 3) * 2];
            #pragma unroll
            for (int nt = 0; nt < 8; nt++) {
                float ex = __expf(acc[mt][nt][2 * dp + 0] - mr);
                float ey = __expf(acc[mt][nt][2 * dp + 1] - mr);
                *(uint32_t*)(base + nt * 8) = bfpack(ex, ey);
            }
        }
    }

    float s = ((lane & 3) == 0) ? (rm[0] + rm[1]) + (rm[2] + rm[3]) : 0.f;
    #pragma unroll
    for (int off = 16; off; off >>= 1) s += __shfl_xor_sync(0xffffffffu, s, off);
    if (lane == 0) s_wred[wid] = s;
    __syncthreads();
    if (tid == 0)
        g_mBpart[blockIdx.x] = (s_wred[0] + s_wred[1]) + (s_wred[2] + s_wred[3]);
}

// ---------------- K2: tensor-core GEMM scan --------------------------------
// One CTA per chunk; warp w owns batch rows 16w..16w+15. Per step:
// V[64,64] <- (V @ A) .* P_t, per-row scaled. Warps fully independent.
__global__ void __launch_bounds__(128) k_scan2() {
    const int c    = blockIdx.x;
    const int wid  = threadIdx.x >> 5;
    const int lane = threadIdx.x & 31;

    __shared__ __align__(16) __nv_bfloat16 V[64][72];

    // A fragments (persistent)
    uint32_t bfr[4][8][2];
    #pragma unroll
    for (int ks = 0; ks < 4; ks++)
        #pragma unroll
        for (int nt = 0; nt < 8; nt++) {
            uint2 u = *(const uint2*)&g_Afrag[ks][nt][lane][0];
            bfr[ks][nt][0] = u.x; bfr[ks][nt][1] = u.y;
        }

    const int wb   = wid * 16;
    const int row0 = wb + (lane >> 2);
    const int row1 = row0 + 8;
    const int c0   = (lane & 3) * 2;

    const int t0 = (c == 0) ? 1 : (CLEN * c - BURN);
    const int t1 = CLEN * c + CLEN;
    const int tb = CLEN * c;

    // init V rows of this warp
    if (c == 0) {
        #pragma unroll 4
        for (int r = 0; r < 16; r++) {
            int row = wb + r;
            int col = lane * 2;
            float2 pf  = bfunpack(*(const uint32_t*)&g_pT[row * 64 + col]);
            float2 pi2 = *(const float2*)&g_pi[col];
            *(uint32_t*)&V[row][col] = bfpack(pi2.x * pf.x, pi2.y * pf.y);
        }
    } else {
        uint32_t one2 = bfpack(1.f, 1.f);
        #pragma unroll 4
        for (int r = 0; r < 16; r++)
            *(uint32_t*)&V[wb + r][lane * 2] = one2;
    }
    __syncwarp();

    // p prefetch ring (depth 2)
    uint32_t pcur[16], pn1[16], pn2[16];
    #pragma unroll
    for (int nt = 0; nt < 8; nt++) {
        size_t ta = (size_t)t0 * 64, tbq = (size_t)(t0 + 1) * 64;
        pcur[2*nt]   = *(const uint32_t*)&g_pT[(ta  + row0) * 64 + nt * 8 + c0];
        pcur[2*nt+1] = *(const uint32_t*)&g_pT[(ta  + row1) * 64 + nt * 8 + c0];
        pn1[2*nt]    = *(const uint32_t*)&g_pT[(tbq + row0) * 64 + nt * 8 + c0];
        pn1[2*nt+1]  = *(const uint32_t*)&g_pT[(tbq + row1) * 64 + nt * 8 + c0];
    }

    double lacc0 = 0.0, lacc1 = 0.0, bnd0 = 0.0, bnd1 = 0.0;
    float msr0 = 1.f, msr1 = 1.f;

    for (int t = t0; t < t1; ++t) {
        const int s = t - t0;
        if (c > 0 && t == tb) {
            bnd0 = (double)logf(msr0) + lacc0;
            bnd1 = (double)logf(msr1) + lacc1;
        }

        float acc[8][4];
        #pragma unroll
        for (int nt = 0; nt < 8; nt++)
            #pragma unroll
            for (int r = 0; r < 4; r++) acc[nt][r] = 0.f;

        #pragma unroll
        for (int ks = 0; ks < 4; ks++) {
            uint32_t a0, a1, a2, a3;
            uint32_t addr = smem_u32(&V[wb + (lane & 15)][ks * 16 + 8 * (lane >> 4)]);
            asm volatile("ldmatrix.sync.aligned.m8n8.x4.shared.b16 {%0,%1,%2,%3}, [%4];"
                         : "=r"(a0), "=r"(a1), "=r"(a2), "=r"(a3) : "r"(addr));
            #pragma unroll
            for (int nt = 0; nt < 8; nt++) {
                asm volatile(
                    "mma.sync.aligned.m16n8k16.row.col.f32.bf16.bf16.f32 "
                    "{%0,%1,%2,%3}, {%4,%5,%6,%7}, {%8,%9}, {%0,%1,%2,%3};"
                    : "+f"(acc[nt][0]), "+f"(acc[nt][1]), "+f"(acc[nt][2]), "+f"(acc[nt][3])
                    : "r"(a0), "r"(a1), "r"(a2), "r"(a3),
                      "r"(bfr[ks][nt][0]), "r"(bfr[ks][nt][1]));
            }
        }

        // prefetch t+2 (g_pT padded)
        {
            size_t tq = (size_t)(t + 2) * 64;
            #pragma unroll
            for (int nt = 0; nt < 8; nt++) {
                pn2[2*nt]   = *(const uint32_t*)&g_pT[(tq + row0) * 64 + nt * 8 + c0];
                pn2[2*nt+1] = *(const uint32_t*)&g_pT[(tq + row1) * 64 + nt * 8 + c0];
            }
        }

        float sc0 = 1.f, sc1 = 1.f;
        if (s > 0 && (s & 7) == 0) {
            sc0 = 1.f / msr0; sc1 = 1.f / msr1;
            lacc0 += (double)logf(msr0);
            lacc1 += (double)logf(msr1);
        }

        float sum0 = 0.f, sum1 = 0.f;
        #pragma unroll
        for (int nt = 0; nt < 8; nt++) {
            float2 pa  = bfunpack(pcur[2*nt]);
            float2 pbv = bfunpack(pcur[2*nt+1]);
            float w00 = acc[nt][0] * pa.x  * sc0;
            float w01 = acc[nt][1] * pa.y  * sc0;
            float w10 = acc[nt][2] * pbv.x * sc1;
            float w11 = acc[nt][3] * pbv.y * sc1;
            sum0 += w00 + w01;
            sum1 += w10 + w11;
            *(uint32_t*)&V[row0][nt * 8 + c0] = bfpack(w00, w01);
            *(uint32_t*)&V[row1][nt * 8 + c0] = bfpack(w10, w11);
        }
        sum0 += __shfl_xor_sync(0xffffffffu, sum0, 1);
        sum0 += __shfl_xor_sync(0xffffffffu, sum0, 2);
        sum1 += __shfl_xor_sync(0xffffffffu, sum1, 1);
        sum1 += __shfl_xor_sync(0xffffffffu, sum1, 2);
        msr0 = sum0;
        msr1 = sum1;

        #pragma unroll
        for (int i = 0; i < 16; i++) { pcur[i] = pn1[i]; pn1[i] = pn2[i]; }
        __syncwarp();
    }

    double end0 = (double)logf(msr0) + lacc0;
    double end1 = (double)logf(msr1) + lacc1;
    if ((lane & 3) == 0) {
        g_chunk[row0 * NCHUNK + c] = end0 - ((c == 0) ? 0.0 : bnd0);
        g_chunk[row1 * NCHUNK + c] = end1 - ((c == 0) ? 0.0 : bnd1);
    }
}

// ---------------- K3: deterministic final sum ------------------------------
__global__ void k_final(float* out) {
    __shared__ double part[BB];
    int b = threadIdx.x;
    double s = 0.0;
    #pragma unroll 16
    for (int cc = 0; cc < NCHUNK; cc++) s += g_chunk[b * NCHUNK + cc];
    float ms = 0.f;
    #pragma unroll 8
    for (int i = 0; i < 64; i++) ms += g_mBpart[b * 64 + i];
    part[b] = s + (double)ms;
    __syncthreads();
    if (b == 0) {
        double tot = 0.0;
        #pragma unroll
        for (int i = 0; i < BB; i++) tot += part[i];
        out[0] = (float)tot;
    }
}

// ---------------- launch ---------------------------------------------------
extern "C" void kernel_launch(void* const* d_in, const int* in_sizes, int n_in,
                              void* d_out, int out_size) {
    const float* X   = (const float*)d_in[0];
    const float* tm  = (const float*)d_in[1];
    const float* pri = (const float*)d_in[2];
    const float* mu  = (const float*)d_in[3];
    const float* lv  = (const float*)d_in[4];

    k_prep<<<1, 64>>>(tm, pri, mu, lv);
    k_emission<<<4096, 128>>>(X);
    k_scan2<<<NCHUNK, 128>>>();
    k_final<<<1, BB>>>((float*)d_out);
}

// round 13
// speedup vs baseline: 3.9675x; 1.0426x over previous
#include <cuda_runtime.h>
#include <cuda_bf16.h>
#include <cstdint>

#define BB 64
#define TLEN 8192
#define DD 64
#define NSTATE 64
#define NCHUNK 256          // chunks per batch (scan)
#define CLEN 32             // payload transitions per chunk
#define BURN 16             // burn-in steps

#define LOG_2PI 1.8378770664093453f

__device__ __forceinline__ uint32_t smem_u32(const void* p) {
    uint32_t a;
    asm("{ .reg .u64 t; cvta.to.shared.u64 t, %1; cvt.u32.u64 %0, t; }" : "=r"(a) : "l"(p));
    return a;
}

__device__ __forceinline__ uint32_t bfpack(float lo, float hi) {
    __nv_bfloat162 h = __floats2bfloat162_rn(lo, hi);
    uint32_t u;
    memcpy(&u, &h, 4);
    return u;
}

__device__ __forceinline__ float2 bfunpack(uint32_t u) {
    __nv_bfloat162 h;
    memcpy(&h, &u, 4);
    return __bfloat1622float2(h);
}

// ---------------- scratch (static device globals; no allocations) ----------
__device__ __align__(16) __nv_bfloat16 g_pT[(size_t)TLEN * BB * NSTATE + 16384]; // p_T[t][b][n], bf16
__device__ float    g_At[NSTATE * NSTATE];       // staging: g_At[j*64+n] = A[n][j]
__device__ uint32_t g_Bfrag[8][8][32][2];        // emission W fragments [ks][nt][lane][r]
__device__ uint32_t g_Afrag[4][8][32][2];        // scan A fragments     [ks][nt][lane][r]
__device__ float    g_bias[NSTATE];
__device__ float    g_pi[NSTATE];
__device__ float    g_mBpart[4096];
__device__ double   g_chunk[BB * NCHUNK];

// ---------------- K0: prep ------------------------------------------------
__global__ void k_prep(const float* __restrict__ tm, const float* __restrict__ priors,
                       const float* __restrict__ mu, const float* __restrict__ lv) {
    int n = threadIdx.x;  // 0..63
    float row[NSTATE];
    float m = -1e30f;
    #pragma unroll
    for (int j = 0; j < NSTATE; j++) { row[j] = tm[n * NSTATE + j]; m = fmaxf(m, row[j]); }
    float s = 0.f;
    #pragma unroll
    for (int j = 0; j < NSTATE; j++) { row[j] = expf(row[j] - m); s += row[j]; }
    float inv = 1.0f / s;
    #pragma unroll
    for (int j = 0; j < NSTATE; j++) g_At[j * NSTATE + n] = row[j] * inv;

    float pm = -1e30f;
    #pragma unroll
    for (int j = 0; j < NSTATE; j++) pm = fmaxf(pm, priors[j]);
    float ps = 0.f;
    #pragma unroll
    for (int j = 0; j < NSTATE; j++) ps += expf(priors[j] - pm);
    g_pi[n] = expf(priors[n] - pm) / ps;

    float w1a[DD], w2a[DD];
    float slv = 0.f, smm = 0.f;
    #pragma unroll
    for (int d = 0; d < DD; d++) {
        float l  = lv[n * DD + d];
        float iv = expf(-l);
        float mu_ = mu[n * DD + d];
        w1a[d] = mu_ * iv;
        w2a[d] = -0.5f * iv;
        slv += l;
        smm += mu_ * mu_ * iv;
    }
    g_bias[n] = -0.5f * ((float)DD * LOG_2PI + slv) - 0.5f * smm;

    // emission B fragments: B[k][col=n] = W[n][k]
    {
        const int nt = n >> 3;
        const int g  = n & 7;
        #pragma unroll
        for (int t = 0; t < 4; t++) {
            int lane = g * 4 + t;
            #pragma unroll
            for (int ks = 0; ks < 8; ks++) {
                #pragma unroll
                for (int r = 0; r < 2; r++) {
                    int k = ks * 16 + t * 2 + r * 8;
                    float v0 = (k < 64) ? w1a[k] : w2a[k - 64];
                    float v1 = (k + 1 < 64) ? w1a[k + 1] : w2a[k + 1 - 64];
                    g_Bfrag[ks][nt][lane][r] = bfpack(v0, v1);
                }
            }
        }
    }
    __syncthreads();
    // scan A fragments: B[k][col=n] = A[k][n] = g_At[n*64+k]
    {
        const int nt = n >> 3;
        const int g  = n & 7;
        const float* arow = &g_At[n * NSTATE];
        #pragma unroll
        for (int t = 0; t < 4; t++) {
            int lane = g * 4 + t;
            #pragma unroll
            for (int ks = 0; ks < 4; ks++) {
                #pragma unroll
                for (int r = 0; r < 2; r++) {
                    int k = ks * 16 + t * 2 + r * 8;
                    g_Afrag[ks][nt][lane][r] = bfpack(arow[k], arow[k + 1]);
                }
            }
        }
    }
}

// ---------------- K1: HMMA emission, register-direct A fragments -----------
// One CTA (128 thr = 4 warps) per 128-row (b,t) tile; no smem staging.
__global__ void __launch_bounds__(128) k_emission(const float* __restrict__ X) {
    __shared__ float s_wred[4];

    const int tid  = threadIdx.x;
    const int wid  = tid >> 5;
    const int lane = tid & 31;
    const int r    = lane >> 2;
    const int c2   = (lane & 3) * 2;
    const int warpbase = wid * 32;
    const size_t tilebase = (size_t)blockIdx.x * 128;

    // A fragments straight from gmem: ks 0-3 = x, ks 4-7 = x^2
    uint32_t afr[2][8][4];
    #pragma unroll
    for (int mt = 0; mt < 2; mt++) {
        const float* row0 = X + (tilebase + warpbase + mt * 16 + r) * 64;
        const float* row1 = row0 + 8 * 64;
        #pragma unroll
        for (int kb = 0; kb < 4; kb++) {
            float2 p00 = *(const float2*)(row0 + 16 * kb + c2);
            float2 p02 = *(const float2*)(row0 + 16 * kb + c2 + 8);
            float2 p10 = *(const float2*)(row1 + 16 * kb + c2);
            float2 p12 = *(const float2*)(row1 + 16 * kb + c2 + 8);
            afr[mt][kb][0] = bfpack(p00.x, p00.y);
            afr[mt][kb][1] = bfpack(p10.x, p10.y);
            afr[mt][kb][2] = bfpack(p02.x, p02.y);
            afr[mt][kb][3] = bfpack(p12.x, p12.y);
            afr[mt][kb + 4][0] = bfpack(p00.x * p00.x, p00.y * p00.y);
            afr[mt][kb + 4][1] = bfpack(p10.x * p10.x, p10.y * p10.y);
            afr[mt][kb + 4][2] = bfpack(p02.x * p02.x, p02.y * p02.y);
            afr[mt][kb + 4][3] = bfpack(p12.x * p12.x, p12.y * p12.y);
        }
    }

    float acc[2][8][4];
    #pragma unroll
    for (int mt = 0; mt < 2; mt++)
        #pragma unroll
        for (int nt = 0; nt < 8; nt++)
            #pragma unroll
            for (int q = 0; q < 4; q++) acc[mt][nt][q] = 0.f;

    #pragma unroll
    for (int ks = 0; ks < 8; ks++) {
        #pragma unroll
        for (int nt = 0; nt < 8; nt++) {
            uint2 b = *(const uint2*)&g_Bfrag[ks][nt][lane][0];
            #pragma unroll
            for (int mt = 0; mt < 2; mt++) {
                asm volatile(
                    "mma.sync.aligned.m16n8k16.row.col.f32.bf16.bf16.f32 "
                    "{%0,%1,%2,%3}, {%4,%5,%6,%7}, {%8,%9}, {%0,%1,%2,%3};"
                    : "+f"(acc[mt][nt][0]), "+f"(acc[mt][nt][1]),
                      "+f"(acc[mt][nt][2]), "+f"(acc[mt][nt][3])
                    : "r"(afr[mt][ks][0]), "r"(afr[mt][ks][1]),
                      "r"(afr[mt][ks][2]), "r"(afr[mt][ks][3]),
                      "r"(b.x), "r"(b.y));
            }
        }
    }

    float2 bload[8];
    #pragma unroll
    for (int nt = 0; nt < 8; nt++)
        bload[nt] = *(const float2*)&g_bias[nt * 8 + c2];

    float rm[4];
    #pragma unroll
    for (int mt = 0; mt < 2; mt++) {
        float m01 = -1e30f, m23 = -1e30f;
        #pragma unroll
        for (int nt = 0; nt < 8; nt++) {
            acc[mt][nt][0] += bload[nt].x;
            acc[mt][nt][1] += bload[nt].y;
            acc[mt][nt][2] += bload[nt].x;
            acc[mt][nt][3] += bload[nt].y;
            m01 = fmaxf(m01, fmaxf(acc[mt][nt][0], acc[mt][nt][1]));
            m23 = fmaxf(m23, fmaxf(acc[mt][nt][2], acc[mt][nt][3]));
        }
        rm[mt * 2 + 0] = m01;
        rm[mt * 2 + 1] = m23;
    }
    #pragma unroll
    for (int j = 0; j < 4; j++) {
        rm[j] = fmaxf(rm[j], __shfl_xor_sync(0xffffffffu, rm[j], 1));
        rm[j] = fmaxf(rm[j], __shfl_xor_sync(0xffffffffu, rm[j], 2));
    }

    // transposed bf16 store: p_T[t][b][n]
    const int b    = blockIdx.x >> 6;
    const int toff = (blockIdx.x & 63) * 128;
    #pragma unroll
    for (int mt = 0; mt < 2; mt++) {
        #pragma unroll
        for (int dp = 0; dp < 2; dp++) {
            const int rloc = warpbase + r + mt * 16 + dp * 8;
            const size_t t = (size_t)(toff + rloc);
            const float mr = rm[mt * 2 + dp];
            __nv_bfloat16* base = &g_pT[(t * 64 + b) * 64 + c2];
            #pragma unroll
            for (int nt = 0; nt < 8; nt++) {
                float ex = __expf(acc[mt][nt][2 * dp + 0] - mr);
                float ey = __expf(acc[mt][nt][2 * dp + 1] - mr);
                *(uint32_t*)(base + nt * 8) = bfpack(ex, ey);
            }
        }
    }

    float s = ((lane & 3) == 0) ? (rm[0] + rm[1]) + (rm[2] + rm[3]) : 0.f;
    #pragma unroll
    for (int off = 16; off; off >>= 1) s += __shfl_xor_sync(0xffffffffu, s, off);
    if (lane == 0) s_wred[wid] = s;
    __syncthreads();
    if (tid == 0)
        g_mBpart[blockIdx.x] = (s_wred[0] + s_wred[1]) + (s_wred[2] + s_wred[3]);
}

// ---------------- K2: tensor-core GEMM scan --------------------------------
// One CTA per chunk; warp w owns batch rows 16w..16w+15. Warps independent.
__global__ void __launch_bounds__(128) k_scan2() {
    const int c    = blockIdx.x;
    const int wid  = threadIdx.x >> 5;
    const int lane = threadIdx.x & 31;

    __shared__ __align__(16) __nv_bfloat16 V[64][72];

    uint32_t bfr[4][8][2];
    #pragma unroll
    for (int ks = 0; ks < 4; ks++)
        #pragma unroll
        for (int nt = 0; nt < 8; nt++) {
            uint2 u = *(const uint2*)&g_Afrag[ks][nt][lane][0];
            bfr[ks][nt][0] = u.x; bfr[ks][nt][1] = u.y;
        }

    const int wb   = wid * 16;
    const int row0 = wb + (lane >> 2);
    const int row1 = row0 + 8;
    const int c0   = (lane & 3) * 2;

    const int t0 = (c == 0) ? 1 : (CLEN * c - BURN);
    const int t1 = CLEN * c + CLEN;
    const int tb = (c == 0) ? -1000 : (CLEN * c);

    if (c == 0) {
        #pragma unroll 4
        for (int r = 0; r < 16; r++) {
            int row = wb + r;
            int col = lane * 2;
            float2 pf  = bfunpack(*(const uint32_t*)&g_pT[row * 64 + col]);
            float2 pi2 = *(const float2*)&g_pi[col];
            *(uint32_t*)&V[row][col] = bfpack(pi2.x * pf.x, pi2.y * pf.y);
        }
    } else {
        uint32_t one2 = bfpack(1.f, 1.f);
        #pragma unroll 4
        for (int r = 0; r < 16; r++)
            *(uint32_t*)&V[wb + r][lane * 2] = one2;
    }
    __syncwarp();

    uint32_t pcur[16], pn1[16], pn2[16];
    #pragma unroll
    for (int nt = 0; nt < 8; nt++) {
        size_t ta = (size_t)t0 * 64, tbq = (size_t)(t0 + 1) * 64;
        pcur[2*nt]   = *(const uint32_t*)&g_pT[(ta  + row0) * 64 + nt * 8 + c0];
        pcur[2*nt+1] = *(const uint32_t*)&g_pT[(ta  + row1) * 64 + nt * 8 + c0];
        pn1[2*nt]    = *(const uint32_t*)&g_pT[(tbq + row0) * 64 + nt * 8 + c0];
        pn1[2*nt+1]  = *(const uint32_t*)&g_pT[(tbq + row1) * 64 + nt * 8 + c0];
    }

    double lacc0 = 0.0, lacc1 = 0.0, bnd0 = 0.0, bnd1 = 0.0;
    float msr0 = 1.f, msr1 = 1.f;

    for (int t = t0; t < t1; ++t) {
        const int s = t - t0;
        if (t == tb) {
            bnd0 = (double)logf(msr0) + lacc0;
            bnd1 = (double)logf(msr1) + lacc1;
        }

        float acc[8][4];
        #pragma unroll
        for (int nt = 0; nt < 8; nt++)
            #pragma unroll
            for (int q = 0; q < 4; q++) acc[nt][q] = 0.f;

        #pragma unroll
        for (int ks = 0; ks < 4; ks++) {
            uint32_t a0, a1, a2, a3;
            uint32_t addr = smem_u32(&V[wb + (lane & 15)][ks * 16 + 8 * (lane >> 4)]);
            asm volatile("ldmatrix.sync.aligned.m8n8.x4.shared.b16 {%0,%1,%2,%3}, [%4];"
                         : "=r"(a0), "=r"(a1), "=r"(a2), "=r"(a3) : "r"(addr));
            #pragma unroll
            for (int nt = 0; nt < 8; nt++) {
                asm volatile(
                    "mma.sync.aligned.m16n8k16.row.col.f32.bf16.bf16.f32 "
                    "{%0,%1,%2,%3}, {%4,%5,%6,%7}, {%8,%9}, {%0,%1,%2,%3};"
                    : "+f"(acc[nt][0]), "+f"(acc[nt][1]), "+f"(acc[nt][2]), "+f"(acc[nt][3])
                    : "r"(a0), "r"(a1), "r"(a2), "r"(a3),
                      "r"(bfr[ks][nt][0]), "r"(bfr[ks][nt][1]));
            }
        }

        {
            size_t tq = (size_t)(t + 2) * 64;
            #pragma unroll
            for (int nt = 0; nt < 8; nt++) {
                pn2[2*nt]   = *(const uint32_t*)&g_pT[(tq + row0) * 64 + nt * 8 + c0];
                pn2[2*nt+1] = *(const uint32_t*)&g_pT[(tq + row1) * 64 + nt * 8 + c0];
            }
        }

        float sc0 = 1.f, sc1 = 1.f;
        if (s > 0 && (s & 7) == 0) {
            sc0 = 1.f / msr0; sc1 = 1.f / msr1;
            lacc0 += (double)logf(msr0);
            lacc1 += (double)logf(msr1);
        }

        const bool do_sum = ((s & 7) == 7) || (t == tb - 1) || (t == t1 - 1);
        float sum0 = 0.f, sum1 = 0.f;
        #pragma unroll
        for (int nt = 0; nt < 8; nt++) {
            float2 pa  = bfunpack(pcur[2*nt]);
            float2 pbv = bfunpack(pcur[2*nt+1]);
            float w00 = acc[nt][0] * pa.x  * sc0;
            float w01 = acc[nt][1] * pa.y  * sc0;
            float w10 = acc[nt][2] * pbv.x * sc1;
            float w11 = acc[nt][3] * pbv.y * sc1;
            sum0 += w00 + w01;
            sum1 += w10 + w11;
            *(uint32_t*)&V[row0][nt * 8 + c0] = bfpack(w00, w01);
            *(uint32_t*)&V[row1][nt * 8 + c0] = bfpack(w10, w11);
        }
        if (do_sum) {
            sum0 += __shfl_xor_sync(0xffffffffu, sum0, 1);
            sum0 += __shfl_xor_sync(0xffffffffu, sum0, 2);
            sum1 += __shfl_xor_sync(0xffffffffu, sum1, 1);
            sum1 += __shfl_xor_sync(0xffffffffu, sum1, 2);
            msr0 = sum0;
            msr1 = sum1;
        }

        #pragma unroll
        for (int i = 0; i < 16; i++) { pcur[i] = pn1[i]; pn1[i] = pn2[i]; }
        __syncwarp();
    }

    double end0 = (double)logf(msr0) + lacc0;
    double end1 = (double)logf(msr1) + lacc1;
    if ((lane & 3) == 0) {
        g_chunk[row0 * NCHUNK + c] = end0 - ((c == 0) ? 0.0 : bnd0);
        g_chunk[row1 * NCHUNK + c] = end1 - ((c == 0) ? 0.0 : bnd1);
    }
}

// ---------------- K3: deterministic final sum (parallel) -------------------
__global__ void __launch_bounds__(256) k_final(float* out) {
    __shared__ double part[BB][4];
    __shared__ double tot[BB];
    const int tid = threadIdx.x;        // 256
    const int b = tid >> 2, q = tid & 3;

    double s = 0.0;
    #pragma unroll 8
    for (int cc = q * 64; cc < q * 64 + 64; cc++) s += g_chunk[b * NCHUNK + cc];
    float ms = 0.f;
    #pragma unroll
    for (int i = q * 16; i < q * 16 + 16; i++) ms += g_mBpart[b * 64 + i];
    part[b][q] = s + (double)ms;
    __syncthreads();
    if (tid < BB)
        tot[tid] = (part[tid][0] + part[tid][1]) + (part[tid][2] + part[tid][3]);
    __syncthreads();
    if (tid == 0) {
        double T = 0.0;
        #pragma unroll
        for (int i = 0; i < BB; i++) T += tot[i];
        out[0] = (float)T;
    }
}

// ---------------- launch ---------------------------------------------------
extern "C" void kernel_launch(void* const* d_in, const int* in_sizes, int n_in,
                              void* d_out, int out_size) {
    const float* X   = (const float*)d_in[0];
    const float* tm  = (const float*)d_in[1];
    const float* pri = (const float*)d_in[2];
    const float* mu  = (const float*)d_in[3];
    const float* lv  = (const float*)d_in[4];

    k_prep<<<1, 64>>>(tm, pri, mu, lv);
    k_emission<<<4096, 128>>>(X);
    k_scan2<<<NCHUNK, 128>>>();
    k_final<<<1, 256>>>((float*)d_out);
}